// round 12
// baseline (speedup 1.0000x reference)
#include <cuda_runtime.h>

#define B_  32
#define T_  4
#define L_  256
#define D_  768
#define H_  12
#define DH_ 64
#define N_  (B_*T_*L_)   // 32768 rows

// ---------------- scratch (no allocations allowed) ----------------
__device__ float g_Hq[(size_t)N_*D_];
__device__ float g_Hk[(size_t)N_*D_];
__device__ float g_Hv[(size_t)N_*D_];
__device__ float g_O [(size_t)N_*D_];
__device__ float g_Y [(size_t)N_*D_];
__device__ unsigned long long g_Mq[(size_t)N_*H_];
__device__ unsigned long long g_Mk[(size_t)N_*H_];

// ---------------- packed f32x2 helpers (sm_103a) ----------------
__device__ __forceinline__ unsigned long long pack2(float lo, float hi) {
    unsigned long long r;
    asm("mov.b64 %0, {%1, %2};" : "=l"(r) : "f"(lo), "f"(hi));
    return r;
}
__device__ __forceinline__ void unpack2(unsigned long long v, float& lo, float& hi) {
    asm("mov.b64 {%0, %1}, %2;" : "=f"(lo), "=f"(hi) : "l"(v));
}
__device__ __forceinline__ unsigned long long ffma2(
    unsigned long long a, unsigned long long b, unsigned long long c) {
    unsigned long long d;
    asm("fma.rn.f32x2 %0, %1, %2, %3;" : "=l"(d) : "l"(a), "l"(b), "l"(c));
    return d;
}

// ====== GEMM (3-way merged): C[z][m,n] = bias[z][n] + sum_k A[m,k]*W[z][n,k] ======
// Single ascending-k FMA chain per element — bitwise-exact vs reference.
// B duplicated (b,b) in smem; rows paired in accumulator -> no packing in hot loop.
// Double-buffered smem: one syncthreads per k0 stage.
__global__ __launch_bounds__(256) void gemm3_kernel(
    const float* __restrict__ A,
    const float* __restrict__ W0, const float* __restrict__ W1, const float* __restrict__ W2,
    const float* __restrict__ b0, const float* __restrict__ b1, const float* __restrict__ b2,
    float* __restrict__ C0, float* __restrict__ C1, float* __restrict__ C2,
    int K, int Nn)
{
    const float* W    = (blockIdx.z == 0) ? W0 : (blockIdx.z == 1) ? W1 : W2;
    const float* bias = (blockIdx.z == 0) ? b0 : (blockIdx.z == 1) ? b1 : b2;
    float*       C    = (blockIdx.z == 0) ? C0 : (blockIdx.z == 1) ? C1 : C2;

    __shared__ float As[2][8][128];                        // 8 KB
    __shared__ unsigned long long Bs[2][8][128];           // 16 KB (b duplicated)
    const int tid  = threadIdx.x;
    const int tx   = tid & 15;
    const int ty   = tid >> 4;
    const int m0   = blockIdx.y * 128;
    const int n0   = blockIdx.x * 128;
    const int arow = tid >> 1;
    const int ak   = (tid & 1) * 4;

    const float* Aptr = A + (size_t)(m0 + arow) * K + ak;
    const float* Wptr = W + (size_t)(n0 + arow) * K + ak;

    unsigned long long acc2[4][8];   // [rowpair][col]: rows 2rp,2rp+1 of this thread
#pragma unroll
    for (int i = 0; i < 4; i++)
#pragma unroll
        for (int j = 0; j < 8; j++) acc2[i][j] = 0ULL;

    // prefetch + store stage 0
    float4 av = *(const float4*)(Aptr);
    float4 wv = *(const float4*)(Wptr);
    As[0][ak + 0][arow] = av.x; As[0][ak + 1][arow] = av.y;
    As[0][ak + 2][arow] = av.z; As[0][ak + 3][arow] = av.w;
    Bs[0][ak + 0][arow] = pack2(wv.x, wv.x);
    Bs[0][ak + 1][arow] = pack2(wv.y, wv.y);
    Bs[0][ak + 2][arow] = pack2(wv.z, wv.z);
    Bs[0][ak + 3][arow] = pack2(wv.w, wv.w);
    __syncthreads();

    int buf = 0;
    for (int k0 = 0; k0 < K; k0 += 8) {
        const bool more = (k0 + 8 < K);
        if (more) {
            av = *(const float4*)(Aptr + k0 + 8);
            wv = *(const float4*)(Wptr + k0 + 8);
        }
#pragma unroll
        for (int kk = 0; kk < 8; kk++) {          // ascending k
            const ulonglong2 a01 = *(const ulonglong2*)&As[buf][kk][ty * 8 + 0];
            const ulonglong2 a23 = *(const ulonglong2*)&As[buf][kk][ty * 8 + 4];
            unsigned long long a2[4];
            a2[0] = a01.x; a2[1] = a01.y; a2[2] = a23.x; a2[3] = a23.y;
            const ulonglong2* bp = (const ulonglong2*)&Bs[buf][kk][tx * 8];
            const ulonglong2 t0 = bp[0], t1 = bp[1], t2 = bp[2], t3 = bp[3];
            unsigned long long b2[8];
            b2[0] = t0.x; b2[1] = t0.y; b2[2] = t1.x; b2[3] = t1.y;
            b2[4] = t2.x; b2[5] = t2.y; b2[6] = t3.x; b2[7] = t3.y;
#pragma unroll
            for (int rp = 0; rp < 4; rp++)
#pragma unroll
                for (int j = 0; j < 8; j++)
                    acc2[rp][j] = ffma2(a2[rp], b2[j], acc2[rp][j]);
        }
        if (more) {
            const int nb = buf ^ 1;
            As[nb][ak + 0][arow] = av.x; As[nb][ak + 1][arow] = av.y;
            As[nb][ak + 2][arow] = av.z; As[nb][ak + 3][arow] = av.w;
            Bs[nb][ak + 0][arow] = pack2(wv.x, wv.x);
            Bs[nb][ak + 1][arow] = pack2(wv.y, wv.y);
            Bs[nb][ak + 2][arow] = pack2(wv.z, wv.z);
            Bs[nb][ak + 3][arow] = pack2(wv.w, wv.w);
            __syncthreads();
            buf = nb;
        }
    }

#pragma unroll
    for (int rp = 0; rp < 4; rp++) {
        float* cp0 = C + (size_t)(m0 + ty * 8 + 2 * rp + 0) * Nn + n0 + tx * 8;
        float* cp1 = C + (size_t)(m0 + ty * 8 + 2 * rp + 1) * Nn + n0 + tx * 8;
#pragma unroll
        for (int j = 0; j < 8; j++) {
            float c0, c1;
            unpack2(acc2[rp][j], c0, c1);
            cp0[j] = __fadd_rn(c0, bias[n0 + tx * 8 + j]);
            cp1[j] = __fadd_rn(c1, bias[n0 + tx * 8 + j]);
        }
    }
}

// ===== LayerNorm + LIF (3-way merged), XLA:CPU NEON-VF8 reduce — order bitwise-fixed =====
__global__ __launch_bounds__(256) void ln3_kernel(
    const float* __restrict__ H0, const float* __restrict__ H1, const float* __restrict__ H2,
    float* __restrict__ S0, float* __restrict__ S1, float* __restrict__ S2,
    const float* __restrict__ g0_, const float* __restrict__ g1_, const float* __restrict__ g2_,
    const float* __restrict__ e0_, const float* __restrict__ e1_, const float* __restrict__ e2_,
    unsigned long long* __restrict__ M0, unsigned long long* __restrict__ M1,
    unsigned long long* __restrict__ M2, float thr)
{
    const float* Hin = (blockIdx.y == 0) ? H0 : (blockIdx.y == 1) ? H1 : H2;
    float*      Sout = (blockIdx.y == 0) ? S0 : (blockIdx.y == 1) ? S1 : S2;
    const float* gam = (blockIdx.y == 0) ? g0_ : (blockIdx.y == 1) ? g1_ : g2_;
    const float* bet = (blockIdx.y == 0) ? e0_ : (blockIdx.y == 1) ? e1_ : e2_;
    unsigned long long* Mout = (blockIdx.y == 0) ? M0 : (blockIdx.y == 1) ? M1 : M2;

    __shared__ float xs[8][768];
    const int w   = threadIdx.x >> 5;
    const int j   = threadIdx.x & 31;
    const int row0 = blockIdx.x * 8 + w;
    const int b   = row0 / L_;
    const int l   = row0 % L_;

    float g[24], be[24], v[24];
#pragma unroll
    for (int k = 0; k < 24; k++) {
        g[k]  = gam[j + 32 * k];
        be[k] = bet[j + 32 * k];
        v[k]  = 0.0f;
    }

    for (int t = 0; t < T_; t++) {
        const size_t row = (size_t)(b * T_ + t) * L_ + l;
        const size_t off = row * D_;
#pragma unroll
        for (int k = 0; k < 24; k++)
            xs[w][j + 32 * k] = Hin[off + j + 32 * k];
        __syncwarp();

        // ---- mean: 8-lane stride-8 serial partials (EXACT order) ----
        float p = 0.0f;
        if (j < 8) {
#pragma unroll 8
            for (int i = 0; i < 96; i++)
                p = __fadd_rn(p, xs[w][8 * i + j]);
        }
        p = __fadd_rn(p, __shfl_xor_sync(0xffffffffu, p, 4));
        p = __fadd_rn(p, __shfl_xor_sync(0xffffffffu, p, 1));
        p = __fadd_rn(p, __shfl_xor_sync(0xffffffffu, p, 2));
        const float sum = __shfl_sync(0xffffffffu, p, 0);
        const float m = __fdiv_rn(sum, 768.0f);

        // ---- variance (EXACT order) ----
        float q = 0.0f;
        if (j < 8) {
#pragma unroll 8
            for (int i = 0; i < 96; i++) {
                const float d = __fsub_rn(xs[w][8 * i + j], m);
                q = __fadd_rn(q, __fmul_rn(d, d));
            }
        }
        q = __fadd_rn(q, __shfl_xor_sync(0xffffffffu, q, 4));
        q = __fadd_rn(q, __shfl_xor_sync(0xffffffffu, q, 1));
        q = __fadd_rn(q, __shfl_xor_sync(0xffffffffu, q, 2));
        const float sum2 = __shfl_sync(0xffffffffu, q, 0);
        const float var = __fdiv_rn(sum2, 768.0f);
        const float rs  = __fsqrt_rn(__fadd_rn(var, 1e-5f));

        // ---- normalize + LIF (EXACT op sequence; *0.5f == /2 bitwise) ----
        unsigned btmp = 0u;
#pragma unroll
        for (int k = 0; k < 24; k++) {
            const float x = xs[w][j + 32 * k];
            const float d = __fsub_rn(x, m);
            const float h = __fadd_rn(__fmul_rn(__fdiv_rn(d, rs), g[k]), be[k]);
            v[k] = __fadd_rn(v[k], __fmul_rn(__fsub_rn(h, v[k]), 0.5f));
            const bool f = (__fsub_rn(v[k], thr) >= 0.0f);
            if (Sout) Sout[off + j + 32 * k] = f ? 1.0f : 0.0f;
            v[k] = f ? 0.0f : v[k];
            if (Mout) {
                const unsigned bal = __ballot_sync(0xffffffffu, f);
                if ((k & 1) == 0) btmp = bal;
                else if (j == (k >> 1))
                    Mout[row * H_ + (k >> 1)] =
                        (unsigned long long)btmp | ((unsigned long long)bal << 32);
            }
        }
        __syncwarp();
    }
}

// ===== attention: QK via mask popcount, AV via dp4a (all exact integers) =====
__global__ __launch_bounds__(256) void attn_kernel(
    const unsigned long long* __restrict__ Mq, const unsigned long long* __restrict__ Mk,
    const float* __restrict__ Sv, float* __restrict__ O)
{
    __shared__ float Vsf[64 * 64];                       // 16 KB staging
    __shared__ __align__(16) unsigned Vs8[64][16];       // [d][mg]: 4 int8 m's per word
    __shared__ unsigned long long Km[64];
    const int h = blockIdx.x;
    const int t = blockIdx.y;
    const int b = blockIdx.z;
    const size_t rowbase = (size_t)(b * T_ + t) * L_;
    const int col = h * DH_;
    const int l = threadIdx.x;

    const unsigned long long qmask = Mq[(rowbase + l) * H_ + h];

    int o32[64];
#pragma unroll
    for (int d = 0; d < 64; d++) o32[d] = 0;

    for (int m0 = 0; m0 < L_; m0 += 64) {
        __syncthreads();
        for (int idx = threadIdx.x; idx < 64 * 64; idx += 256) {
            const int m = idx >> 6;
            const int d = idx & 63;
            Vsf[idx] = Sv[(rowbase + m0 + m) * D_ + col + d];
        }
        if (threadIdx.x < 64)
            Km[threadIdx.x] = Mk[(rowbase + m0 + threadIdx.x) * H_ + h];
        __syncthreads();
        // pack V tile int8 d-major: Vs8[d][mg] = bytes of m = 4mg..4mg+3
        for (int wv = threadIdx.x; wv < 1024; wv += 256) {
            const int d  = wv >> 4;
            const int mg = wv & 15;
            unsigned r = 0;
            if (Vsf[(4 * mg + 0) * 64 + d] > 0.5f) r |= 1u;
            if (Vsf[(4 * mg + 1) * 64 + d] > 0.5f) r |= 1u << 8;
            if (Vsf[(4 * mg + 2) * 64 + d] > 0.5f) r |= 1u << 16;
            if (Vsf[(4 * mg + 3) * 64 + d] > 0.5f) r |= 1u << 24;
            Vs8[d][mg] = r;
        }
        __syncthreads();

#pragma unroll 1
        for (int mq = 0; mq < 4; mq++) {     // 16 m's per mq
            unsigned a4[4];
#pragma unroll
            for (int r = 0; r < 4; r++) {
                const int mg = mq * 4 + r;
                const int a0 = __popcll(qmask & Km[4 * mg + 0]);
                const int a1 = __popcll(qmask & Km[4 * mg + 1]);
                const int a2 = __popcll(qmask & Km[4 * mg + 2]);
                const int a3 = __popcll(qmask & Km[4 * mg + 3]);
                a4[r] = (unsigned)a0 | ((unsigned)a1 << 8) |
                        ((unsigned)a2 << 16) | ((unsigned)a3 << 24);
            }
#pragma unroll
            for (int d = 0; d < 64; d++) {
                const uint4 vv = *(const uint4*)&Vs8[d][mq * 4];
                int acc = o32[d];
                acc = __dp4a((int)a4[0], (int)vv.x, acc);
                acc = __dp4a((int)a4[1], (int)vv.y, acc);
                acc = __dp4a((int)a4[2], (int)vv.z, acc);
                acc = __dp4a((int)a4[3], (int)vv.w, acc);
                o32[d] = acc;
            }
        }
    }

    float* op = O + (rowbase + l) * D_ + col;
#pragma unroll
    for (int d = 0; d < 64; d += 4) {
        float4 v4;
        v4.x = __fmul_rn((float)o32[d + 0], 0.25f);   // exact
        v4.y = __fmul_rn((float)o32[d + 1], 0.25f);
        v4.z = __fmul_rn((float)o32[d + 2], 0.25f);
        v4.w = __fmul_rn((float)o32[d + 3], 0.25f);
        *(float4*)(op + d) = v4;
    }
}

// ========== LIF over T on O (thr = 0.5, exact dyadic), in place, float4 ==========
__global__ __launch_bounds__(256) void lif2_kernel(float4* __restrict__ IO)
{
    const int nq = (L_ * D_) / 4;
    const int idx = blockIdx.x * 256 + threadIdx.x;   // over B*L*D/4
    const int b = idx / nq;
    const int r = idx % nq;
    float4 v = make_float4(0.f, 0.f, 0.f, 0.f);
#pragma unroll
    for (int t = 0; t < T_; t++) {
        const size_t off = ((size_t)(b * T_ + t)) * (size_t)nq + r;
        float4 x = IO[off];
        v.x = __fadd_rn(v.x, __fmul_rn(__fsub_rn(x.x, v.x), 0.5f));
        v.y = __fadd_rn(v.y, __fmul_rn(__fsub_rn(x.y, v.y), 0.5f));
        v.z = __fadd_rn(v.z, __fmul_rn(__fsub_rn(x.z, v.z), 0.5f));
        v.w = __fadd_rn(v.w, __fmul_rn(__fsub_rn(x.w, v.w), 0.5f));
        const bool f0 = (v.x >= 0.5f), f1 = (v.y >= 0.5f);
        const bool f2 = (v.z >= 0.5f), f3 = (v.w >= 0.5f);
        IO[off] = make_float4(f0 ? 1.f : 0.f, f1 ? 1.f : 0.f,
                              f2 ? 1.f : 0.f, f3 ? 1.f : 0.f);
        v.x = f0 ? 0.f : v.x;
        v.y = f1 ? 0.f : v.y;
        v.z = f2 ? 0.f : v.z;
        v.w = f3 ? 0.f : v.w;
    }
}

// ================= launch =================
extern "C" void kernel_launch(void* const* d_in, const int* in_sizes, int n_in,
                              void* d_out, int out_size)
{
    (void)in_sizes; (void)n_in; (void)out_size;
    const float* x   = (const float*)d_in[0];
    const float* qw  = (const float*)d_in[1];
    const float* qb  = (const float*)d_in[2];
    const float* qg  = (const float*)d_in[3];
    const float* qbe = (const float*)d_in[4];
    const float* kw  = (const float*)d_in[5];
    const float* kb  = (const float*)d_in[6];
    const float* kg  = (const float*)d_in[7];
    const float* kbe = (const float*)d_in[8];
    const float* vw  = (const float*)d_in[9];
    const float* vb  = (const float*)d_in[10];
    const float* vg  = (const float*)d_in[11];
    const float* vbe = (const float*)d_in[12];
    const float* lw  = (const float*)d_in[13];
    const float* lb  = (const float*)d_in[14];
    const float* lg  = (const float*)d_in[15];
    const float* lbe = (const float*)d_in[16];

    float *Hq, *Hk, *Hv, *O, *Y;
    unsigned long long *Mq, *Mk;
    cudaGetSymbolAddress((void**)&Hq, g_Hq);
    cudaGetSymbolAddress((void**)&Hk, g_Hk);
    cudaGetSymbolAddress((void**)&Hv, g_Hv);
    cudaGetSymbolAddress((void**)&O,  g_O);
    cudaGetSymbolAddress((void**)&Y,  g_Y);
    cudaGetSymbolAddress((void**)&Mq, g_Mq);
    cudaGetSymbolAddress((void**)&Mk, g_Mk);

    // Q/K/V projections in ONE launch
    gemm3_kernel<<<dim3(D_ / 128, N_ / 128, 3), 256>>>(
        x, qw, kw, vw, qb, kb, vb, Hq, Hk, Hv, D_, D_);

    // 3 LNs in ONE launch: Q,K emit masks only; V emits float spikes
    ln3_kernel<<<dim3((B_ * L_) / 8, 3), 256>>>(
        Hq, Hk, Hv,
        nullptr, nullptr, Hv,
        qg, kg, vg, qbe, kbe, vbe,
        Mq, Mk, nullptr, 1.0f);

    // attention per (h,t,b) — mask QK + dp4a AV (exact integers)
    attn_kernel<<<dim3(H_, T_, B_), 256>>>(Mq, Mk, Hv, O);

    // LIF (thr=0.5) over T, exact dyadic, in place -> binary
    lif2_kernel<<<(B_ * L_ * D_) / 1024, 256>>>((float4*)O);

    // final linear on binary spikes
    gemm3_kernel<<<dim3(D_ / 128, N_ / 128, 1), 256>>>(
        O, lw, lw, lw, lb, lb, lb, Y, Y, Y, D_, D_);

    // final LN + LIF (thr=1) -> output [B,T,L,D]; no masks
    ln3_kernel<<<dim3((B_ * L_) / 8, 1), 256>>>(
        Y, Y, Y,
        (float*)d_out, (float*)d_out, (float*)d_out,
        lg, lg, lg, lbe, lbe, lbe,
        nullptr, nullptr, nullptr, 1.0f);
}

// round 13
// speedup vs baseline: 2.3126x; 2.3126x over previous
#include <cuda_runtime.h>

#define B_  32
#define T_  4
#define L_  256
#define D_  768
#define H_  12
#define DH_ 64
#define N_  (B_*T_*L_)   // 32768 rows

// ---------------- scratch (no allocations allowed) ----------------
__device__ float g_Hq[(size_t)N_*D_];
__device__ float g_Hk[(size_t)N_*D_];
__device__ float g_Hv[(size_t)N_*D_];
__device__ float g_O [(size_t)N_*D_];
__device__ float g_Y [(size_t)N_*D_];
__device__ unsigned long long g_Mq[(size_t)N_*H_];
__device__ unsigned long long g_Mk[(size_t)N_*H_];

// ---------------- packed f32x2 helpers (sm_103a) ----------------
__device__ __forceinline__ unsigned long long pack2(float lo, float hi) {
    unsigned long long r;
    asm("mov.b64 %0, {%1, %2};" : "=l"(r) : "f"(lo), "f"(hi));
    return r;
}
__device__ __forceinline__ void unpack2(unsigned long long v, float& lo, float& hi) {
    asm("mov.b64 {%0, %1}, %2;" : "=f"(lo), "=f"(hi) : "l"(v));
}
__device__ __forceinline__ unsigned long long ffma2(
    unsigned long long a, unsigned long long b, unsigned long long c) {
    unsigned long long d;
    asm("fma.rn.f32x2 %0, %1, %2, %3;" : "=l"(d) : "l"(a), "l"(b), "l"(c));
    return d;
}

// ====== GEMM (3-way merged): C[z][m,n] = bias[z][n] + sum_k A[m,k]*W[z][n,k] ======
// Single ascending-k FMA chain per element — bitwise-exact vs reference. DO NOT reorder.
// (R11 version — proven fastest; register-lean with per-kk a-pack.)
__global__ __launch_bounds__(256) void gemm3_kernel(
    const float* __restrict__ A,
    const float* __restrict__ W0, const float* __restrict__ W1, const float* __restrict__ W2,
    const float* __restrict__ b0, const float* __restrict__ b1, const float* __restrict__ b2,
    float* __restrict__ C0, float* __restrict__ C1, float* __restrict__ C2,
    int K, int Nn)
{
    const float* W    = (blockIdx.z == 0) ? W0 : (blockIdx.z == 1) ? W1 : W2;
    const float* bias = (blockIdx.z == 0) ? b0 : (blockIdx.z == 1) ? b1 : b2;
    float*       C    = (blockIdx.z == 0) ? C0 : (blockIdx.z == 1) ? C1 : C2;

    __shared__ float As[8][128];
    __shared__ float Bs[8][128];
    const int tid  = threadIdx.x;
    const int tx   = tid & 15;
    const int ty   = tid >> 4;
    const int m0   = blockIdx.y * 128;
    const int n0   = blockIdx.x * 128;
    const int arow = tid >> 1;
    const int ak   = (tid & 1) * 4;

    const float* Aptr = A + (size_t)(m0 + arow) * K + ak;
    const float* Wptr = W + (size_t)(n0 + arow) * K + ak;

    unsigned long long acc2[8][4];
#pragma unroll
    for (int i = 0; i < 8; i++)
#pragma unroll
        for (int j = 0; j < 4; j++) acc2[i][j] = 0ULL;

    for (int k0 = 0; k0 < K; k0 += 8) {
        float4 av = *(const float4*)(Aptr + k0);
        float4 wv = *(const float4*)(Wptr + k0);
        __syncthreads();
        As[ak + 0][arow] = av.x; As[ak + 1][arow] = av.y;
        As[ak + 2][arow] = av.z; As[ak + 3][arow] = av.w;
        Bs[ak + 0][arow] = wv.x; Bs[ak + 1][arow] = wv.y;
        Bs[ak + 2][arow] = wv.z; Bs[ak + 3][arow] = wv.w;
        __syncthreads();
#pragma unroll
        for (int kk = 0; kk < 8; kk++) {          // ascending k
            float a[8];
            *(float4*)&a[0] = *(const float4*)&As[kk][ty * 8 + 0];
            *(float4*)&a[4] = *(const float4*)&As[kk][ty * 8 + 4];
            const ulonglong2 b01 = *(const ulonglong2*)&Bs[kk][tx * 8 + 0];
            const ulonglong2 b23 = *(const ulonglong2*)&Bs[kk][tx * 8 + 4];
            unsigned long long b2[4];
            b2[0] = b01.x; b2[1] = b01.y; b2[2] = b23.x; b2[3] = b23.y;
#pragma unroll
            for (int i = 0; i < 8; i++) {
                const unsigned long long a2 = pack2(a[i], a[i]);
#pragma unroll
                for (int j = 0; j < 4; j++)
                    acc2[i][j] = ffma2(a2, b2[j], acc2[i][j]);
            }
        }
    }

#pragma unroll
    for (int i = 0; i < 8; i++) {
        float* cp = C + (size_t)(m0 + ty * 8 + i) * Nn + n0 + tx * 8;
#pragma unroll
        for (int j = 0; j < 4; j++) {
            float c0, c1;
            unpack2(acc2[i][j], c0, c1);
            cp[2 * j + 0] = __fadd_rn(c0, bias[n0 + tx * 8 + 2 * j + 0]);
            cp[2 * j + 1] = __fadd_rn(c1, bias[n0 + tx * 8 + 2 * j + 1]);
        }
    }
}

// ===== LayerNorm + LIF (3-way merged), XLA:CPU NEON-VF8 reduce — order bitwise-fixed =====
__global__ __launch_bounds__(256) void ln3_kernel(
    const float* __restrict__ H0, const float* __restrict__ H1, const float* __restrict__ H2,
    float* __restrict__ S0, float* __restrict__ S1, float* __restrict__ S2,
    const float* __restrict__ g0_, const float* __restrict__ g1_, const float* __restrict__ g2_,
    const float* __restrict__ e0_, const float* __restrict__ e1_, const float* __restrict__ e2_,
    unsigned long long* __restrict__ M0, unsigned long long* __restrict__ M1,
    unsigned long long* __restrict__ M2, float thr)
{
    const float* Hin = (blockIdx.y == 0) ? H0 : (blockIdx.y == 1) ? H1 : H2;
    float*      Sout = (blockIdx.y == 0) ? S0 : (blockIdx.y == 1) ? S1 : S2;
    const float* gam = (blockIdx.y == 0) ? g0_ : (blockIdx.y == 1) ? g1_ : g2_;
    const float* bet = (blockIdx.y == 0) ? e0_ : (blockIdx.y == 1) ? e1_ : e2_;
    unsigned long long* Mout = (blockIdx.y == 0) ? M0 : (blockIdx.y == 1) ? M1 : M2;

    __shared__ float xs[8][768];
    const int w   = threadIdx.x >> 5;
    const int j   = threadIdx.x & 31;
    const int row0 = blockIdx.x * 8 + w;
    const int b   = row0 / L_;
    const int l   = row0 % L_;

    float g[24], be[24], v[24];
#pragma unroll
    for (int k = 0; k < 24; k++) {
        g[k]  = gam[j + 32 * k];
        be[k] = bet[j + 32 * k];
        v[k]  = 0.0f;
    }

    for (int t = 0; t < T_; t++) {
        const size_t row = (size_t)(b * T_ + t) * L_ + l;
        const size_t off = row * D_;
#pragma unroll
        for (int k = 0; k < 24; k++)
            xs[w][j + 32 * k] = Hin[off + j + 32 * k];
        __syncwarp();

        // ---- mean: 8-lane stride-8 serial partials (EXACT order) ----
        float p = 0.0f;
        if (j < 8) {
#pragma unroll 8
            for (int i = 0; i < 96; i++)
                p = __fadd_rn(p, xs[w][8 * i + j]);
        }
        p = __fadd_rn(p, __shfl_xor_sync(0xffffffffu, p, 4));
        p = __fadd_rn(p, __shfl_xor_sync(0xffffffffu, p, 1));
        p = __fadd_rn(p, __shfl_xor_sync(0xffffffffu, p, 2));
        const float sum = __shfl_sync(0xffffffffu, p, 0);
        const float m = __fdiv_rn(sum, 768.0f);

        // ---- variance (EXACT order) ----
        float q = 0.0f;
        if (j < 8) {
#pragma unroll 8
            for (int i = 0; i < 96; i++) {
                const float d = __fsub_rn(xs[w][8 * i + j], m);
                q = __fadd_rn(q, __fmul_rn(d, d));
            }
        }
        q = __fadd_rn(q, __shfl_xor_sync(0xffffffffu, q, 4));
        q = __fadd_rn(q, __shfl_xor_sync(0xffffffffu, q, 1));
        q = __fadd_rn(q, __shfl_xor_sync(0xffffffffu, q, 2));
        const float sum2 = __shfl_sync(0xffffffffu, q, 0);
        const float var = __fdiv_rn(sum2, 768.0f);
        const float rs  = __fsqrt_rn(__fadd_rn(var, 1e-5f));

        // ---- normalize + LIF (EXACT op sequence; *0.5f == /2 bitwise) ----
        unsigned btmp = 0u;
#pragma unroll
        for (int k = 0; k < 24; k++) {
            const float x = xs[w][j + 32 * k];
            const float d = __fsub_rn(x, m);
            const float h = __fadd_rn(__fmul_rn(__fdiv_rn(d, rs), g[k]), be[k]);
            v[k] = __fadd_rn(v[k], __fmul_rn(__fsub_rn(h, v[k]), 0.5f));
            const bool f = (__fsub_rn(v[k], thr) >= 0.0f);
            if (Sout) Sout[off + j + 32 * k] = f ? 1.0f : 0.0f;
            v[k] = f ? 0.0f : v[k];
            if (Mout) {
                const unsigned bal = __ballot_sync(0xffffffffu, f);
                if ((k & 1) == 0) btmp = bal;
                else if (j == (k >> 1))
                    Mout[row * H_ + (k >> 1)] =
                        (unsigned long long)btmp | ((unsigned long long)bal << 32);
            }
        }
        __syncwarp();
    }
}

// ===== attention: QK via mask popcount, AV via dp4a (all exact integers) =====
__global__ __launch_bounds__(256) void attn_kernel(
    const unsigned long long* __restrict__ Mq, const unsigned long long* __restrict__ Mk,
    const float* __restrict__ Sv, float* __restrict__ O)
{
    __shared__ float Vsf[64 * 64];                       // 16 KB staging
    __shared__ __align__(16) unsigned Vs8[64][16];       // [d][mg]: 4 int8 m's per word
    __shared__ unsigned long long Km[64];
    const int h = blockIdx.x;
    const int t = blockIdx.y;
    const int b = blockIdx.z;
    const size_t rowbase = (size_t)(b * T_ + t) * L_;
    const int col = h * DH_;
    const int l = threadIdx.x;

    const unsigned long long qmask = Mq[(rowbase + l) * H_ + h];

    int o32[64];
#pragma unroll
    for (int d = 0; d < 64; d++) o32[d] = 0;

    for (int m0 = 0; m0 < L_; m0 += 64) {
        __syncthreads();
        for (int idx = threadIdx.x; idx < 64 * 64; idx += 256) {
            const int m = idx >> 6;
            const int d = idx & 63;
            Vsf[idx] = Sv[(rowbase + m0 + m) * D_ + col + d];
        }
        if (threadIdx.x < 64)
            Km[threadIdx.x] = Mk[(rowbase + m0 + threadIdx.x) * H_ + h];
        __syncthreads();
        // pack V tile int8 d-major: Vs8[d][mg] = bytes of m = 4mg..4mg+3
        for (int wv = threadIdx.x; wv < 1024; wv += 256) {
            const int d  = wv >> 4;
            const int mg = wv & 15;
            unsigned r = 0;
            if (Vsf[(4 * mg + 0) * 64 + d] > 0.5f) r |= 1u;
            if (Vsf[(4 * mg + 1) * 64 + d] > 0.5f) r |= 1u << 8;
            if (Vsf[(4 * mg + 2) * 64 + d] > 0.5f) r |= 1u << 16;
            if (Vsf[(4 * mg + 3) * 64 + d] > 0.5f) r |= 1u << 24;
            Vs8[d][mg] = r;
        }
        __syncthreads();

#pragma unroll 1
        for (int mq = 0; mq < 4; mq++) {     // 16 m's per mq
            unsigned a4[4];
#pragma unroll
            for (int r = 0; r < 4; r++) {
                const int mg = mq * 4 + r;
                const int a0 = __popcll(qmask & Km[4 * mg + 0]);
                const int a1 = __popcll(qmask & Km[4 * mg + 1]);
                const int a2 = __popcll(qmask & Km[4 * mg + 2]);
                const int a3 = __popcll(qmask & Km[4 * mg + 3]);
                a4[r] = (unsigned)a0 | ((unsigned)a1 << 8) |
                        ((unsigned)a2 << 16) | ((unsigned)a3 << 24);
            }
#pragma unroll
            for (int d = 0; d < 64; d++) {
                const uint4 vv = *(const uint4*)&Vs8[d][mq * 4];
                int acc = o32[d];
                acc = __dp4a((int)a4[0], (int)vv.x, acc);
                acc = __dp4a((int)a4[1], (int)vv.y, acc);
                acc = __dp4a((int)a4[2], (int)vv.z, acc);
                acc = __dp4a((int)a4[3], (int)vv.w, acc);
                o32[d] = acc;
            }
        }
    }

    float* op = O + (rowbase + l) * D_ + col;
#pragma unroll
    for (int d = 0; d < 64; d += 4) {
        float4 v4;
        v4.x = __fmul_rn((float)o32[d + 0], 0.25f);   // exact
        v4.y = __fmul_rn((float)o32[d + 1], 0.25f);
        v4.z = __fmul_rn((float)o32[d + 2], 0.25f);
        v4.w = __fmul_rn((float)o32[d + 3], 0.25f);
        *(float4*)(op + d) = v4;
    }
}

// ========== LIF over T on O (thr = 0.5, exact dyadic), in place, float4 ==========
__global__ __launch_bounds__(256) void lif2_kernel(float4* __restrict__ IO)
{
    const int nq = (L_ * D_) / 4;
    const int idx = blockIdx.x * 256 + threadIdx.x;   // over B*L*D/4
    const int b = idx / nq;
    const int r = idx % nq;
    float4 v = make_float4(0.f, 0.f, 0.f, 0.f);
#pragma unroll
    for (int t = 0; t < T_; t++) {
        const size_t off = ((size_t)(b * T_ + t)) * (size_t)nq + r;
        float4 x = IO[off];
        v.x = __fadd_rn(v.x, __fmul_rn(__fsub_rn(x.x, v.x), 0.5f));
        v.y = __fadd_rn(v.y, __fmul_rn(__fsub_rn(x.y, v.y), 0.5f));
        v.z = __fadd_rn(v.z, __fmul_rn(__fsub_rn(x.z, v.z), 0.5f));
        v.w = __fadd_rn(v.w, __fmul_rn(__fsub_rn(x.w, v.w), 0.5f));
        const bool f0 = (v.x >= 0.5f), f1 = (v.y >= 0.5f);
        const bool f2 = (v.z >= 0.5f), f3 = (v.w >= 0.5f);
        IO[off] = make_float4(f0 ? 1.f : 0.f, f1 ? 1.f : 0.f,
                              f2 ? 1.f : 0.f, f3 ? 1.f : 0.f);
        v.x = f0 ? 0.f : v.x;
        v.y = f1 ? 0.f : v.y;
        v.z = f2 ? 0.f : v.z;
        v.w = f3 ? 0.f : v.w;
    }
}

// ================= launch =================
extern "C" void kernel_launch(void* const* d_in, const int* in_sizes, int n_in,
                              void* d_out, int out_size)
{
    (void)in_sizes; (void)n_in; (void)out_size;
    const float* x   = (const float*)d_in[0];
    const float* qw  = (const float*)d_in[1];
    const float* qb  = (const float*)d_in[2];
    const float* qg  = (const float*)d_in[3];
    const float* qbe = (const float*)d_in[4];
    const float* kw  = (const float*)d_in[5];
    const float* kb  = (const float*)d_in[6];
    const float* kg  = (const float*)d_in[7];
    const float* kbe = (const float*)d_in[8];
    const float* vw  = (const float*)d_in[9];
    const float* vb  = (const float*)d_in[10];
    const float* vg  = (const float*)d_in[11];
    const float* vbe = (const float*)d_in[12];
    const float* lw  = (const float*)d_in[13];
    const float* lb  = (const float*)d_in[14];
    const float* lg  = (const float*)d_in[15];
    const float* lbe = (const float*)d_in[16];

    float *Hq, *Hk, *Hv, *O, *Y;
    unsigned long long *Mq, *Mk;
    cudaGetSymbolAddress((void**)&Hq, g_Hq);
    cudaGetSymbolAddress((void**)&Hk, g_Hk);
    cudaGetSymbolAddress((void**)&Hv, g_Hv);
    cudaGetSymbolAddress((void**)&O,  g_O);
    cudaGetSymbolAddress((void**)&Y,  g_Y);
    cudaGetSymbolAddress((void**)&Mq, g_Mq);
    cudaGetSymbolAddress((void**)&Mk, g_Mk);

    // Q/K/V projections in ONE launch
    gemm3_kernel<<<dim3(D_ / 128, N_ / 128, 3), 256>>>(
        x, qw, kw, vw, qb, kb, vb, Hq, Hk, Hv, D_, D_);

    // 3 LNs in ONE launch: Q,K emit masks only; V emits float spikes
    ln3_kernel<<<dim3((B_ * L_) / 8, 3), 256>>>(
        Hq, Hk, Hv,
        nullptr, nullptr, Hv,
        qg, kg, vg, qbe, kbe, vbe,
        Mq, Mk, nullptr, 1.0f);

    // attention per (h,t,b) — mask QK + dp4a AV (exact integers)
    attn_kernel<<<dim3(H_, T_, B_), 256>>>(Mq, Mk, Hv, O);

    // LIF (thr=0.5) over T, exact dyadic, in place -> binary
    lif2_kernel<<<(B_ * L_ * D_) / 1024, 256>>>((float4*)O);

    // final linear on binary spikes
    gemm3_kernel<<<dim3(D_ / 128, N_ / 128, 1), 256>>>(
        O, lw, lw, lw, lb, lb, lb, Y, Y, Y, D_, D_);

    // final LN + LIF (thr=1) -> output [B,T,L,D]; no masks
    ln3_kernel<<<dim3((B_ * L_) / 8, 1), 256>>>(
        Y, Y, Y,
        (float*)d_out, (float*)d_out, (float*)d_out,
        lg, lg, lg, lbe, lbe, lbe,
        nullptr, nullptr, nullptr, 1.0f);
}

// round 14
// speedup vs baseline: 2.4362x; 1.0534x over previous
#include <cuda_runtime.h>

#define B_  32
#define T_  4
#define L_  256
#define D_  768
#define H_  12
#define DH_ 64
#define N_  (B_*T_*L_)   // 32768 rows

// ---------------- scratch (no allocations allowed) ----------------
__device__ float g_Hq[(size_t)N_*D_];
__device__ float g_Hk[(size_t)N_*D_];
__device__ float g_Hv[(size_t)N_*D_];
__device__ float g_O [(size_t)N_*D_];
__device__ float g_Y [(size_t)N_*D_];
__device__ unsigned long long g_Mq[(size_t)N_*H_];
__device__ unsigned long long g_Mk[(size_t)N_*H_];

// ---------------- packed f32x2 helpers (sm_103a) ----------------
__device__ __forceinline__ unsigned long long pack2(float lo, float hi) {
    unsigned long long r;
    asm("mov.b64 %0, {%1, %2};" : "=l"(r) : "f"(lo), "f"(hi));
    return r;
}
__device__ __forceinline__ void unpack2(unsigned long long v, float& lo, float& hi) {
    asm("mov.b64 {%0, %1}, %2;" : "=f"(lo), "=f"(hi) : "l"(v));
}
__device__ __forceinline__ unsigned long long ffma2(
    unsigned long long a, unsigned long long b, unsigned long long c) {
    unsigned long long d;
    asm("fma.rn.f32x2 %0, %1, %2, %3;" : "=l"(d) : "l"(a), "l"(b), "l"(c));
    return d;
}

// ====== GEMM (3-way merged): C[z][m,n] = bias[z][n] + sum_k A[m,k]*W[n,k] ======
// Single ascending-k FMA chain per element — bitwise-exact vs reference. DO NOT reorder.
// R13 layout + register prefetch: next-stage global loads issue BEFORE compute,
// so the 256-FFMA2 block hides global latency. Single smem buffer, 2 syncs/stage.
__global__ __launch_bounds__(256) void gemm3_kernel(
    const float* __restrict__ A,
    const float* __restrict__ W0, const float* __restrict__ W1, const float* __restrict__ W2,
    const float* __restrict__ b0, const float* __restrict__ b1, const float* __restrict__ b2,
    float* __restrict__ C0, float* __restrict__ C1, float* __restrict__ C2,
    int K, int Nn)
{
    const float* W    = (blockIdx.z == 0) ? W0 : (blockIdx.z == 1) ? W1 : W2;
    const float* bias = (blockIdx.z == 0) ? b0 : (blockIdx.z == 1) ? b1 : b2;
    float*       C    = (blockIdx.z == 0) ? C0 : (blockIdx.z == 1) ? C1 : C2;

    __shared__ float As[8][128];
    __shared__ float Bs[8][128];
    const int tid  = threadIdx.x;
    const int tx   = tid & 15;
    const int ty   = tid >> 4;
    const int m0   = blockIdx.y * 128;
    const int n0   = blockIdx.x * 128;
    const int arow = tid >> 1;
    const int ak   = (tid & 1) * 4;

    const float* Aptr = A + (size_t)(m0 + arow) * K + ak;
    const float* Wptr = W + (size_t)(n0 + arow) * K + ak;

    unsigned long long acc2[8][4];
#pragma unroll
    for (int i = 0; i < 8; i++)
#pragma unroll
        for (int j = 0; j < 4; j++) acc2[i][j] = 0ULL;

    float4 av = *(const float4*)(Aptr);
    float4 wv = *(const float4*)(Wptr);

    for (int k0 = 0; k0 < K; k0 += 8) {
        __syncthreads();                  // previous stage's consumers done
        As[ak + 0][arow] = av.x; As[ak + 1][arow] = av.y;
        As[ak + 2][arow] = av.z; As[ak + 3][arow] = av.w;
        Bs[ak + 0][arow] = wv.x; Bs[ak + 1][arow] = wv.y;
        Bs[ak + 2][arow] = wv.z; Bs[ak + 3][arow] = wv.w;
        __syncthreads();
        if (k0 + 8 < K) {                 // issue next-stage loads EARLY
            av = *(const float4*)(Aptr + k0 + 8);
            wv = *(const float4*)(Wptr + k0 + 8);
        }
#pragma unroll
        for (int kk = 0; kk < 8; kk++) {          // ascending k
            float a[8];
            *(float4*)&a[0] = *(const float4*)&As[kk][ty * 8 + 0];
            *(float4*)&a[4] = *(const float4*)&As[kk][ty * 8 + 4];
            const ulonglong2 b01 = *(const ulonglong2*)&Bs[kk][tx * 8 + 0];
            const ulonglong2 b23 = *(const ulonglong2*)&Bs[kk][tx * 8 + 4];
            unsigned long long b2[4];
            b2[0] = b01.x; b2[1] = b01.y; b2[2] = b23.x; b2[3] = b23.y;
#pragma unroll
            for (int i = 0; i < 8; i++) {
                const unsigned long long a2 = pack2(a[i], a[i]);
#pragma unroll
                for (int j = 0; j < 4; j++)
                    acc2[i][j] = ffma2(a2, b2[j], acc2[i][j]);
            }
        }
    }

#pragma unroll
    for (int i = 0; i < 8; i++) {
        float* cp = C + (size_t)(m0 + ty * 8 + i) * Nn + n0 + tx * 8;
#pragma unroll
        for (int j = 0; j < 4; j++) {
            float c0, c1;
            unpack2(acc2[i][j], c0, c1);
            cp[2 * j + 0] = __fadd_rn(c0, bias[n0 + tx * 8 + 2 * j + 0]);
            cp[2 * j + 1] = __fadd_rn(c1, bias[n0 + tx * 8 + 2 * j + 1]);
        }
    }
}

// ===== LayerNorm + LIF (3-way merged), XLA:CPU NEON-VF8 reduce — order bitwise-fixed =====
__global__ __launch_bounds__(256) void ln3_kernel(
    const float* __restrict__ H0, const float* __restrict__ H1, const float* __restrict__ H2,
    float* __restrict__ S0, float* __restrict__ S1, float* __restrict__ S2,
    const float* __restrict__ g0_, const float* __restrict__ g1_, const float* __restrict__ g2_,
    const float* __restrict__ e0_, const float* __restrict__ e1_, const float* __restrict__ e2_,
    unsigned long long* __restrict__ M0, unsigned long long* __restrict__ M1,
    unsigned long long* __restrict__ M2, float thr)
{
    const float* Hin = (blockIdx.y == 0) ? H0 : (blockIdx.y == 1) ? H1 : H2;
    float*      Sout = (blockIdx.y == 0) ? S0 : (blockIdx.y == 1) ? S1 : S2;
    const float* gam = (blockIdx.y == 0) ? g0_ : (blockIdx.y == 1) ? g1_ : g2_;
    const float* bet = (blockIdx.y == 0) ? e0_ : (blockIdx.y == 1) ? e1_ : e2_;
    unsigned long long* Mout = (blockIdx.y == 0) ? M0 : (blockIdx.y == 1) ? M1 : M2;

    __shared__ float xs[8][768];
    const int w   = threadIdx.x >> 5;
    const int j   = threadIdx.x & 31;
    const int row0 = blockIdx.x * 8 + w;
    const int b   = row0 / L_;
    const int l   = row0 % L_;

    float g[24], be[24], v[24];
#pragma unroll
    for (int k = 0; k < 24; k++) {
        g[k]  = gam[j + 32 * k];
        be[k] = bet[j + 32 * k];
        v[k]  = 0.0f;
    }

    for (int t = 0; t < T_; t++) {
        const size_t row = (size_t)(b * T_ + t) * L_ + l;
        const size_t off = row * D_;
#pragma unroll
        for (int k = 0; k < 24; k++)
            xs[w][j + 32 * k] = Hin[off + j + 32 * k];
        __syncwarp();

        // ---- mean: 8-lane stride-8 serial partials (EXACT order) ----
        float p = 0.0f;
        if (j < 8) {
#pragma unroll 8
            for (int i = 0; i < 96; i++)
                p = __fadd_rn(p, xs[w][8 * i + j]);
        }
        p = __fadd_rn(p, __shfl_xor_sync(0xffffffffu, p, 4));
        p = __fadd_rn(p, __shfl_xor_sync(0xffffffffu, p, 1));
        p = __fadd_rn(p, __shfl_xor_sync(0xffffffffu, p, 2));
        const float sum = __shfl_sync(0xffffffffu, p, 0);
        const float m = __fdiv_rn(sum, 768.0f);

        // ---- variance (EXACT order) ----
        float q = 0.0f;
        if (j < 8) {
#pragma unroll 8
            for (int i = 0; i < 96; i++) {
                const float d = __fsub_rn(xs[w][8 * i + j], m);
                q = __fadd_rn(q, __fmul_rn(d, d));
            }
        }
        q = __fadd_rn(q, __shfl_xor_sync(0xffffffffu, q, 4));
        q = __fadd_rn(q, __shfl_xor_sync(0xffffffffu, q, 1));
        q = __fadd_rn(q, __shfl_xor_sync(0xffffffffu, q, 2));
        const float sum2 = __shfl_sync(0xffffffffu, q, 0);
        const float var = __fdiv_rn(sum2, 768.0f);
        const float rs  = __fsqrt_rn(__fadd_rn(var, 1e-5f));

        // ---- normalize + LIF (EXACT op sequence; *0.5f == /2 bitwise) ----
        unsigned btmp = 0u;
#pragma unroll
        for (int k = 0; k < 24; k++) {
            const float x = xs[w][j + 32 * k];
            const float d = __fsub_rn(x, m);
            const float h = __fadd_rn(__fmul_rn(__fdiv_rn(d, rs), g[k]), be[k]);
            v[k] = __fadd_rn(v[k], __fmul_rn(__fsub_rn(h, v[k]), 0.5f));
            const bool f = (__fsub_rn(v[k], thr) >= 0.0f);
            if (Sout) Sout[off + j + 32 * k] = f ? 1.0f : 0.0f;
            v[k] = f ? 0.0f : v[k];
            if (Mout) {
                const unsigned bal = __ballot_sync(0xffffffffu, f);
                if ((k & 1) == 0) btmp = bal;
                else if (j == (k >> 1))
                    Mout[row * H_ + (k >> 1)] =
                        (unsigned long long)btmp | ((unsigned long long)bal << 32);
            }
        }
        __syncwarp();
    }
}

// ===== attention: QK via mask popcount, AV via dp4a (all exact integers) =====
__global__ __launch_bounds__(256) void attn_kernel(
    const unsigned long long* __restrict__ Mq, const unsigned long long* __restrict__ Mk,
    const float* __restrict__ Sv, float* __restrict__ O)
{
    __shared__ float Vsf[64 * 64];                       // 16 KB staging
    __shared__ __align__(16) unsigned Vs8[64][16];       // [d][mg]: 4 int8 m's per word
    __shared__ unsigned long long Km[64];
    const int h = blockIdx.x;
    const int t = blockIdx.y;
    const int b = blockIdx.z;
    const size_t rowbase = (size_t)(b * T_ + t) * L_;
    const int col = h * DH_;
    const int l = threadIdx.x;

    const unsigned long long qmask = Mq[(rowbase + l) * H_ + h];

    int o32[64];
#pragma unroll
    for (int d = 0; d < 64; d++) o32[d] = 0;

    for (int m0 = 0; m0 < L_; m0 += 64) {
        __syncthreads();
        for (int idx = threadIdx.x; idx < 64 * 64; idx += 256) {
            const int m = idx >> 6;
            const int d = idx & 63;
            Vsf[idx] = Sv[(rowbase + m0 + m) * D_ + col + d];
        }
        if (threadIdx.x < 64)
            Km[threadIdx.x] = Mk[(rowbase + m0 + threadIdx.x) * H_ + h];
        __syncthreads();
        // pack V tile int8 d-major: Vs8[d][mg] = bytes of m = 4mg..4mg+3
        for (int wv = threadIdx.x; wv < 1024; wv += 256) {
            const int d  = wv >> 4;
            const int mg = wv & 15;
            unsigned r = 0;
            if (Vsf[(4 * mg + 0) * 64 + d] > 0.5f) r |= 1u;
            if (Vsf[(4 * mg + 1) * 64 + d] > 0.5f) r |= 1u << 8;
            if (Vsf[(4 * mg + 2) * 64 + d] > 0.5f) r |= 1u << 16;
            if (Vsf[(4 * mg + 3) * 64 + d] > 0.5f) r |= 1u << 24;
            Vs8[d][mg] = r;
        }
        __syncthreads();

#pragma unroll 1
        for (int mq = 0; mq < 4; mq++) {     // 16 m's per mq
            unsigned a4[4];
#pragma unroll
            for (int r = 0; r < 4; r++) {
                const int mg = mq * 4 + r;
                const int a0 = __popcll(qmask & Km[4 * mg + 0]);
                const int a1 = __popcll(qmask & Km[4 * mg + 1]);
                const int a2 = __popcll(qmask & Km[4 * mg + 2]);
                const int a3 = __popcll(qmask & Km[4 * mg + 3]);
                a4[r] = (unsigned)a0 | ((unsigned)a1 << 8) |
                        ((unsigned)a2 << 16) | ((unsigned)a3 << 24);
            }
#pragma unroll
            for (int d = 0; d < 64; d++) {
                const uint4 vv = *(const uint4*)&Vs8[d][mq * 4];
                int acc = o32[d];
                acc = __dp4a((int)a4[0], (int)vv.x, acc);
                acc = __dp4a((int)a4[1], (int)vv.y, acc);
                acc = __dp4a((int)a4[2], (int)vv.z, acc);
                acc = __dp4a((int)a4[3], (int)vv.w, acc);
                o32[d] = acc;
            }
        }
    }

    float* op = O + (rowbase + l) * D_ + col;
#pragma unroll
    for (int d = 0; d < 64; d += 4) {
        float4 v4;
        v4.x = __fmul_rn((float)o32[d + 0], 0.25f);   // exact
        v4.y = __fmul_rn((float)o32[d + 1], 0.25f);
        v4.z = __fmul_rn((float)o32[d + 2], 0.25f);
        v4.w = __fmul_rn((float)o32[d + 3], 0.25f);
        *(float4*)(op + d) = v4;
    }
}

// ========== LIF over T on O (thr = 0.5, exact dyadic), in place, float4 ==========
__global__ __launch_bounds__(256) void lif2_kernel(float4* __restrict__ IO)
{
    const int nq = (L_ * D_) / 4;
    const int idx = blockIdx.x * 256 + threadIdx.x;   // over B*L*D/4
    const int b = idx / nq;
    const int r = idx % nq;
    float4 v = make_float4(0.f, 0.f, 0.f, 0.f);
#pragma unroll
    for (int t = 0; t < T_; t++) {
        const size_t off = ((size_t)(b * T_ + t)) * (size_t)nq + r;
        float4 x = IO[off];
        v.x = __fadd_rn(v.x, __fmul_rn(__fsub_rn(x.x, v.x), 0.5f));
        v.y = __fadd_rn(v.y, __fmul_rn(__fsub_rn(x.y, v.y), 0.5f));
        v.z = __fadd_rn(v.z, __fmul_rn(__fsub_rn(x.z, v.z), 0.5f));
        v.w = __fadd_rn(v.w, __fmul_rn(__fsub_rn(x.w, v.w), 0.5f));
        const bool f0 = (v.x >= 0.5f), f1 = (v.y >= 0.5f);
        const bool f2 = (v.z >= 0.5f), f3 = (v.w >= 0.5f);
        IO[off] = make_float4(f0 ? 1.f : 0.f, f1 ? 1.f : 0.f,
                              f2 ? 1.f : 0.f, f3 ? 1.f : 0.f);
        v.x = f0 ? 0.f : v.x;
        v.y = f1 ? 0.f : v.y;
        v.z = f2 ? 0.f : v.z;
        v.w = f3 ? 0.f : v.w;
    }
}

// ================= launch =================
extern "C" void kernel_launch(void* const* d_in, const int* in_sizes, int n_in,
                              void* d_out, int out_size)
{
    (void)in_sizes; (void)n_in; (void)out_size;
    const float* x   = (const float*)d_in[0];
    const float* qw  = (const float*)d_in[1];
    const float* qb  = (const float*)d_in[2];
    const float* qg  = (const float*)d_in[3];
    const float* qbe = (const float*)d_in[4];
    const float* kw  = (const float*)d_in[5];
    const float* kb  = (const float*)d_in[6];
    const float* kg  = (const float*)d_in[7];
    const float* kbe = (const float*)d_in[8];
    const float* vw  = (const float*)d_in[9];
    const float* vb  = (const float*)d_in[10];
    const float* vg  = (const float*)d_in[11];
    const float* vbe = (const float*)d_in[12];
    const float* lw  = (const float*)d_in[13];
    const float* lb  = (const float*)d_in[14];
    const float* lg  = (const float*)d_in[15];
    const float* lbe = (const float*)d_in[16];

    float *Hq, *Hk, *Hv, *O, *Y;
    unsigned long long *Mq, *Mk;
    cudaGetSymbolAddress((void**)&Hq, g_Hq);
    cudaGetSymbolAddress((void**)&Hk, g_Hk);
    cudaGetSymbolAddress((void**)&Hv, g_Hv);
    cudaGetSymbolAddress((void**)&O,  g_O);
    cudaGetSymbolAddress((void**)&Y,  g_Y);
    cudaGetSymbolAddress((void**)&Mq, g_Mq);
    cudaGetSymbolAddress((void**)&Mk, g_Mk);

    // Q/K/V projections in ONE launch
    gemm3_kernel<<<dim3(D_ / 128, N_ / 128, 3), 256>>>(
        x, qw, kw, vw, qb, kb, vb, Hq, Hk, Hv, D_, D_);

    // 3 LNs in ONE launch: Q,K emit masks only; V emits float spikes
    ln3_kernel<<<dim3((B_ * L_) / 8, 3), 256>>>(
        Hq, Hk, Hv,
        nullptr, nullptr, Hv,
        qg, kg, vg, qbe, kbe, vbe,
        Mq, Mk, nullptr, 1.0f);

    // attention per (h,t,b) — mask QK + dp4a AV (exact integers)
    attn_kernel<<<dim3(H_, T_, B_), 256>>>(Mq, Mk, Hv, O);

    // LIF (thr=0.5) over T, exact dyadic, in place -> binary
    lif2_kernel<<<(B_ * L_ * D_) / 1024, 256>>>((float4*)O);

    // final linear on binary spikes
    gemm3_kernel<<<dim3(D_ / 128, N_ / 128, 1), 256>>>(
        O, lw, lw, lw, lb, lb, lb, Y, Y, Y, D_, D_);

    // final LN + LIF (thr=1) -> output [B,T,L,D]; no masks
    ln3_kernel<<<dim3((B_ * L_) / 8, 1), 256>>>(
        Y, Y, Y,
        (float*)d_out, (float*)d_out, (float*)d_out,
        lg, lg, lg, lbe, lbe, lbe,
        nullptr, nullptr, nullptr, 1.0f);
}

// round 15
// speedup vs baseline: 2.4424x; 1.0025x over previous
#include <cuda_runtime.h>

#define B_  32
#define T_  4
#define L_  256
#define D_  768
#define H_  12
#define DH_ 64
#define N_  (B_*T_*L_)   // 32768 rows

// ---------------- scratch (no allocations allowed) ----------------
__device__ float g_Hq[(size_t)N_*D_];
__device__ float g_Hk[(size_t)N_*D_];
__device__ float g_Hv[(size_t)N_*D_];
__device__ float g_O [(size_t)N_*D_];
__device__ float g_Y [(size_t)N_*D_];
__device__ unsigned long long g_Mq[(size_t)N_*H_];
__device__ unsigned long long g_Mk[(size_t)N_*H_];

// ---------------- packed f32x2 helpers (sm_103a) ----------------
__device__ __forceinline__ unsigned long long pack2(float lo, float hi) {
    unsigned long long r;
    asm("mov.b64 %0, {%1, %2};" : "=l"(r) : "f"(lo), "f"(hi));
    return r;
}
__device__ __forceinline__ void unpack2(unsigned long long v, float& lo, float& hi) {
    asm("mov.b64 {%0, %1}, %2;" : "=f"(lo), "=f"(hi) : "l"(v));
}
__device__ __forceinline__ unsigned long long ffma2(
    unsigned long long a, unsigned long long b, unsigned long long c) {
    unsigned long long d;
    asm("fma.rn.f32x2 %0, %1, %2, %3;" : "=l"(d) : "l"(a), "l"(b), "l"(c));
    return d;
}

// ====== GEMM (3-way merged): C[z][m,n] = bias[z][n] + sum_k A[m,k]*W[n,k] ======
// Single ascending-k FMA chain per element — bitwise-exact vs reference. DO NOT reorder.
// R14 inner loop + double-buffered smem: ONE __syncthreads per stage.
__global__ __launch_bounds__(256) void gemm3_kernel(
    const float* __restrict__ A,
    const float* __restrict__ W0, const float* __restrict__ W1, const float* __restrict__ W2,
    const float* __restrict__ b0, const float* __restrict__ b1, const float* __restrict__ b2,
    float* __restrict__ C0, float* __restrict__ C1, float* __restrict__ C2,
    int K, int Nn)
{
    const float* W    = (blockIdx.z == 0) ? W0 : (blockIdx.z == 1) ? W1 : W2;
    const float* bias = (blockIdx.z == 0) ? b0 : (blockIdx.z == 1) ? b1 : b2;
    float*       C    = (blockIdx.z == 0) ? C0 : (blockIdx.z == 1) ? C1 : C2;

    __shared__ float As[2][8][128];
    __shared__ float Bs[2][8][128];
    const int tid  = threadIdx.x;
    const int tx   = tid & 15;
    const int ty   = tid >> 4;
    const int m0   = blockIdx.y * 128;
    const int n0   = blockIdx.x * 128;
    const int arow = tid >> 1;
    const int ak   = (tid & 1) * 4;

    const float* Aptr = A + (size_t)(m0 + arow) * K + ak;
    const float* Wptr = W + (size_t)(n0 + arow) * K + ak;

    unsigned long long acc2[8][4];
#pragma unroll
    for (int i = 0; i < 8; i++)
#pragma unroll
        for (int j = 0; j < 4; j++) acc2[i][j] = 0ULL;

    float4 av = *(const float4*)(Aptr);
    float4 wv = *(const float4*)(Wptr);
    // store stage 0 into buffer 0
    As[0][ak + 0][arow] = av.x; As[0][ak + 1][arow] = av.y;
    As[0][ak + 2][arow] = av.z; As[0][ak + 3][arow] = av.w;
    Bs[0][ak + 0][arow] = wv.x; Bs[0][ak + 1][arow] = wv.y;
    Bs[0][ak + 2][arow] = wv.z; Bs[0][ak + 3][arow] = wv.w;
    __syncthreads();

    int buf = 0;
    for (int k0 = 0; k0 < K; k0 += 8) {
        const bool more = (k0 + 8 < K);
        if (more) {                       // issue next-stage loads EARLY
            av = *(const float4*)(Aptr + k0 + 8);
            wv = *(const float4*)(Wptr + k0 + 8);
        }
#pragma unroll
        for (int kk = 0; kk < 8; kk++) {          // ascending k
            float a[8];
            *(float4*)&a[0] = *(const float4*)&As[buf][kk][ty * 8 + 0];
            *(float4*)&a[4] = *(const float4*)&As[buf][kk][ty * 8 + 4];
            const ulonglong2 b01 = *(const ulonglong2*)&Bs[buf][kk][tx * 8 + 0];
            const ulonglong2 b23 = *(const ulonglong2*)&Bs[buf][kk][tx * 8 + 4];
            unsigned long long b2[4];
            b2[0] = b01.x; b2[1] = b01.y; b2[2] = b23.x; b2[3] = b23.y;
#pragma unroll
            for (int i = 0; i < 8; i++) {
                const unsigned long long a2 = pack2(a[i], a[i]);
#pragma unroll
                for (int j = 0; j < 4; j++)
                    acc2[i][j] = ffma2(a2, b2[j], acc2[i][j]);
            }
        }
        if (more) {
            const int nb = buf ^ 1;       // no warp reads nb anymore (post-barrier)
            As[nb][ak + 0][arow] = av.x; As[nb][ak + 1][arow] = av.y;
            As[nb][ak + 2][arow] = av.z; As[nb][ak + 3][arow] = av.w;
            Bs[nb][ak + 0][arow] = wv.x; Bs[nb][ak + 1][arow] = wv.y;
            Bs[nb][ak + 2][arow] = wv.z; Bs[nb][ak + 3][arow] = wv.w;
            __syncthreads();              // single barrier per stage
            buf = nb;
        }
    }

#pragma unroll
    for (int i = 0; i < 8; i++) {
        float* cp = C + (size_t)(m0 + ty * 8 + i) * Nn + n0 + tx * 8;
#pragma unroll
        for (int j = 0; j < 4; j++) {
            float c0, c1;
            unpack2(acc2[i][j], c0, c1);
            cp[2 * j + 0] = __fadd_rn(c0, bias[n0 + tx * 8 + 2 * j + 0]);
            cp[2 * j + 1] = __fadd_rn(c1, bias[n0 + tx * 8 + 2 * j + 1]);
        }
    }
}

// ===== LayerNorm + LIF (3-way merged), XLA:CPU NEON-VF8 reduce — order bitwise-fixed =====
__global__ __launch_bounds__(256) void ln3_kernel(
    const float* __restrict__ H0, const float* __restrict__ H1, const float* __restrict__ H2,
    float* __restrict__ S0, float* __restrict__ S1, float* __restrict__ S2,
    const float* __restrict__ g0_, const float* __restrict__ g1_, const float* __restrict__ g2_,
    const float* __restrict__ e0_, const float* __restrict__ e1_, const float* __restrict__ e2_,
    unsigned long long* __restrict__ M0, unsigned long long* __restrict__ M1,
    unsigned long long* __restrict__ M2, float thr)
{
    const float* Hin = (blockIdx.y == 0) ? H0 : (blockIdx.y == 1) ? H1 : H2;
    float*      Sout = (blockIdx.y == 0) ? S0 : (blockIdx.y == 1) ? S1 : S2;
    const float* gam = (blockIdx.y == 0) ? g0_ : (blockIdx.y == 1) ? g1_ : g2_;
    const float* bet = (blockIdx.y == 0) ? e0_ : (blockIdx.y == 1) ? e1_ : e2_;
    unsigned long long* Mout = (blockIdx.y == 0) ? M0 : (blockIdx.y == 1) ? M1 : M2;

    __shared__ float xs[8][768];
    const int w   = threadIdx.x >> 5;
    const int j   = threadIdx.x & 31;
    const int row0 = blockIdx.x * 8 + w;
    const int b   = row0 / L_;
    const int l   = row0 % L_;

    float g[24], be[24], v[24];
#pragma unroll
    for (int k = 0; k < 24; k++) {
        g[k]  = gam[j + 32 * k];
        be[k] = bet[j + 32 * k];
        v[k]  = 0.0f;
    }

    for (int t = 0; t < T_; t++) {
        const size_t row = (size_t)(b * T_ + t) * L_ + l;
        const size_t off = row * D_;
#pragma unroll
        for (int k = 0; k < 24; k++)
            xs[w][j + 32 * k] = Hin[off + j + 32 * k];
        __syncwarp();

        // ---- mean: 8-lane stride-8 serial partials (EXACT order) ----
        float p = 0.0f;
        if (j < 8) {
#pragma unroll 8
            for (int i = 0; i < 96; i++)
                p = __fadd_rn(p, xs[w][8 * i + j]);
        }
        p = __fadd_rn(p, __shfl_xor_sync(0xffffffffu, p, 4));
        p = __fadd_rn(p, __shfl_xor_sync(0xffffffffu, p, 1));
        p = __fadd_rn(p, __shfl_xor_sync(0xffffffffu, p, 2));
        const float sum = __shfl_sync(0xffffffffu, p, 0);
        const float m = __fdiv_rn(sum, 768.0f);

        // ---- variance (EXACT order) ----
        float q = 0.0f;
        if (j < 8) {
#pragma unroll 8
            for (int i = 0; i < 96; i++) {
                const float d = __fsub_rn(xs[w][8 * i + j], m);
                q = __fadd_rn(q, __fmul_rn(d, d));
            }
        }
        q = __fadd_rn(q, __shfl_xor_sync(0xffffffffu, q, 4));
        q = __fadd_rn(q, __shfl_xor_sync(0xffffffffu, q, 1));
        q = __fadd_rn(q, __shfl_xor_sync(0xffffffffu, q, 2));
        const float sum2 = __shfl_sync(0xffffffffu, q, 0);
        const float var = __fdiv_rn(sum2, 768.0f);
        const float rs  = __fsqrt_rn(__fadd_rn(var, 1e-5f));

        // ---- normalize + LIF (EXACT op sequence; *0.5f == /2 bitwise) ----
        unsigned btmp = 0u;
#pragma unroll
        for (int k = 0; k < 24; k++) {
            const float x = xs[w][j + 32 * k];
            const float d = __fsub_rn(x, m);
            const float h = __fadd_rn(__fmul_rn(__fdiv_rn(d, rs), g[k]), be[k]);
            v[k] = __fadd_rn(v[k], __fmul_rn(__fsub_rn(h, v[k]), 0.5f));
            const bool f = (__fsub_rn(v[k], thr) >= 0.0f);
            if (Sout) Sout[off + j + 32 * k] = f ? 1.0f : 0.0f;
            v[k] = f ? 0.0f : v[k];
            if (Mout) {
                const unsigned bal = __ballot_sync(0xffffffffu, f);
                if ((k & 1) == 0) btmp = bal;
                else if (j == (k >> 1))
                    Mout[row * H_ + (k >> 1)] =
                        (unsigned long long)btmp | ((unsigned long long)bal << 32);
            }
        }
        __syncwarp();
    }
}

// ===== attention: QK via mask popcount, AV via dp4a (all exact integers) =====
__global__ __launch_bounds__(256) void attn_kernel(
    const unsigned long long* __restrict__ Mq, const unsigned long long* __restrict__ Mk,
    const float* __restrict__ Sv, float* __restrict__ O)
{
    __shared__ float Vsf[64 * 64];                       // 16 KB staging
    __shared__ __align__(16) unsigned Vs8[64][16];       // [d][mg]: 4 int8 m's per word
    __shared__ unsigned long long Km[64];
    const int h = blockIdx.x;
    const int t = blockIdx.y;
    const int b = blockIdx.z;
    const size_t rowbase = (size_t)(b * T_ + t) * L_;
    const int col = h * DH_;
    const int l = threadIdx.x;

    const unsigned long long qmask = Mq[(rowbase + l) * H_ + h];

    int o32[64];
#pragma unroll
    for (int d = 0; d < 64; d++) o32[d] = 0;

    for (int m0 = 0; m0 < L_; m0 += 64) {
        __syncthreads();
        for (int idx = threadIdx.x; idx < 64 * 64; idx += 256) {
            const int m = idx >> 6;
            const int d = idx & 63;
            Vsf[idx] = Sv[(rowbase + m0 + m) * D_ + col + d];
        }
        if (threadIdx.x < 64)
            Km[threadIdx.x] = Mk[(rowbase + m0 + threadIdx.x) * H_ + h];
        __syncthreads();
        // pack V tile int8 d-major: Vs8[d][mg] = bytes of m = 4mg..4mg+3
        for (int wv = threadIdx.x; wv < 1024; wv += 256) {
            const int d  = wv >> 4;
            const int mg = wv & 15;
            unsigned r = 0;
            if (Vsf[(4 * mg + 0) * 64 + d] > 0.5f) r |= 1u;
            if (Vsf[(4 * mg + 1) * 64 + d] > 0.5f) r |= 1u << 8;
            if (Vsf[(4 * mg + 2) * 64 + d] > 0.5f) r |= 1u << 16;
            if (Vsf[(4 * mg + 3) * 64 + d] > 0.5f) r |= 1u << 24;
            Vs8[d][mg] = r;
        }
        __syncthreads();

#pragma unroll 1
        for (int mq = 0; mq < 4; mq++) {     // 16 m's per mq
            unsigned a4[4];
#pragma unroll
            for (int r = 0; r < 4; r++) {
                const int mg = mq * 4 + r;
                const int a0 = __popcll(qmask & Km[4 * mg + 0]);
                const int a1 = __popcll(qmask & Km[4 * mg + 1]);
                const int a2 = __popcll(qmask & Km[4 * mg + 2]);
                const int a3 = __popcll(qmask & Km[4 * mg + 3]);
                a4[r] = (unsigned)a0 | ((unsigned)a1 << 8) |
                        ((unsigned)a2 << 16) | ((unsigned)a3 << 24);
            }
#pragma unroll
            for (int d = 0; d < 64; d++) {
                const uint4 vv = *(const uint4*)&Vs8[d][mq * 4];
                int acc = o32[d];
                acc = __dp4a((int)a4[0], (int)vv.x, acc);
                acc = __dp4a((int)a4[1], (int)vv.y, acc);
                acc = __dp4a((int)a4[2], (int)vv.z, acc);
                acc = __dp4a((int)a4[3], (int)vv.w, acc);
                o32[d] = acc;
            }
        }
    }

    float* op = O + (rowbase + l) * D_ + col;
#pragma unroll
    for (int d = 0; d < 64; d += 4) {
        float4 v4;
        v4.x = __fmul_rn((float)o32[d + 0], 0.25f);   // exact
        v4.y = __fmul_rn((float)o32[d + 1], 0.25f);
        v4.z = __fmul_rn((float)o32[d + 2], 0.25f);
        v4.w = __fmul_rn((float)o32[d + 3], 0.25f);
        *(float4*)(op + d) = v4;
    }
}

// ========== LIF over T on O (thr = 0.5, exact dyadic), in place, float4 ==========
__global__ __launch_bounds__(256) void lif2_kernel(float4* __restrict__ IO)
{
    const int nq = (L_ * D_) / 4;
    const int idx = blockIdx.x * 256 + threadIdx.x;   // over B*L*D/4
    const int b = idx / nq;
    const int r = idx % nq;
    float4 v = make_float4(0.f, 0.f, 0.f, 0.f);
#pragma unroll
    for (int t = 0; t < T_; t++) {
        const size_t off = ((size_t)(b * T_ + t)) * (size_t)nq + r;
        float4 x = IO[off];
        v.x = __fadd_rn(v.x, __fmul_rn(__fsub_rn(x.x, v.x), 0.5f));
        v.y = __fadd_rn(v.y, __fmul_rn(__fsub_rn(x.y, v.y), 0.5f));
        v.z = __fadd_rn(v.z, __fmul_rn(__fsub_rn(x.z, v.z), 0.5f));
        v.w = __fadd_rn(v.w, __fmul_rn(__fsub_rn(x.w, v.w), 0.5f));
        const bool f0 = (v.x >= 0.5f), f1 = (v.y >= 0.5f);
        const bool f2 = (v.z >= 0.5f), f3 = (v.w >= 0.5f);
        IO[off] = make_float4(f0 ? 1.f : 0.f, f1 ? 1.f : 0.f,
                              f2 ? 1.f : 0.f, f3 ? 1.f : 0.f);
        v.x = f0 ? 0.f : v.x;
        v.y = f1 ? 0.f : v.y;
        v.z = f2 ? 0.f : v.z;
        v.w = f3 ? 0.f : v.w;
    }
}

// ================= launch =================
extern "C" void kernel_launch(void* const* d_in, const int* in_sizes, int n_in,
                              void* d_out, int out_size)
{
    (void)in_sizes; (void)n_in; (void)out_size;
    const float* x   = (const float*)d_in[0];
    const float* qw  = (const float*)d_in[1];
    const float* qb  = (const float*)d_in[2];
    const float* qg  = (const float*)d_in[3];
    const float* qbe = (const float*)d_in[4];
    const float* kw  = (const float*)d_in[5];
    const float* kb  = (const float*)d_in[6];
    const float* kg  = (const float*)d_in[7];
    const float* kbe = (const float*)d_in[8];
    const float* vw  = (const float*)d_in[9];
    const float* vb  = (const float*)d_in[10];
    const float* vg  = (const float*)d_in[11];
    const float* vbe = (const float*)d_in[12];
    const float* lw  = (const float*)d_in[13];
    const float* lb  = (const float*)d_in[14];
    const float* lg  = (const float*)d_in[15];
    const float* lbe = (const float*)d_in[16];

    float *Hq, *Hk, *Hv, *O, *Y;
    unsigned long long *Mq, *Mk;
    cudaGetSymbolAddress((void**)&Hq, g_Hq);
    cudaGetSymbolAddress((void**)&Hk, g_Hk);
    cudaGetSymbolAddress((void**)&Hv, g_Hv);
    cudaGetSymbolAddress((void**)&O,  g_O);
    cudaGetSymbolAddress((void**)&Y,  g_Y);
    cudaGetSymbolAddress((void**)&Mq, g_Mq);
    cudaGetSymbolAddress((void**)&Mk, g_Mk);

    // Q/K/V projections in ONE launch
    gemm3_kernel<<<dim3(D_ / 128, N_ / 128, 3), 256>>>(
        x, qw, kw, vw, qb, kb, vb, Hq, Hk, Hv, D_, D_);

    // 3 LNs in ONE launch: Q,K emit masks only; V emits float spikes
    ln3_kernel<<<dim3((B_ * L_) / 8, 3), 256>>>(
        Hq, Hk, Hv,
        nullptr, nullptr, Hv,
        qg, kg, vg, qbe, kbe, vbe,
        Mq, Mk, nullptr, 1.0f);

    // attention per (h,t,b) — mask QK + dp4a AV (exact integers)
    attn_kernel<<<dim3(H_, T_, B_), 256>>>(Mq, Mk, Hv, O);

    // LIF (thr=0.5) over T, exact dyadic, in place -> binary
    lif2_kernel<<<(B_ * L_ * D_) / 1024, 256>>>((float4*)O);

    // final linear on binary spikes
    gemm3_kernel<<<dim3(D_ / 128, N_ / 128, 1), 256>>>(
        O, lw, lw, lw, lb, lb, lb, Y, Y, Y, D_, D_);

    // final LN + LIF (thr=1) -> output [B,T,L,D]; no masks
    ln3_kernel<<<dim3((B_ * L_) / 8, 1), 256>>>(
        Y, Y, Y,
        (float*)d_out, (float*)d_out, (float*)d_out,
        lg, lg, lg, lbe, lbe, lbe,
        nullptr, nullptr, nullptr, 1.0f);
}

// round 16
// speedup vs baseline: 2.5728x; 1.0534x over previous
#include <cuda_runtime.h>

#define B_  32
#define T_  4
#define L_  256
#define D_  768
#define H_  12
#define DH_ 64
#define N_  (B_*T_*L_)   // 32768 rows

// ---------------- scratch (no allocations allowed) ----------------
__device__ float g_Hq[(size_t)N_*D_];
__device__ float g_Hk[(size_t)N_*D_];
__device__ float g_Hv[(size_t)N_*D_];
__device__ float g_O [(size_t)N_*D_];
__device__ float g_Y [(size_t)N_*D_];
__device__ unsigned long long g_Mq[(size_t)N_*H_];
__device__ unsigned long long g_Mk[(size_t)N_*H_];
__device__ unsigned long long g_Mv[(size_t)N_*H_];

// ---------------- packed f32x2 helpers (sm_103a) ----------------
__device__ __forceinline__ unsigned long long pack2(float lo, float hi) {
    unsigned long long r;
    asm("mov.b64 %0, {%1, %2};" : "=l"(r) : "f"(lo), "f"(hi));
    return r;
}
__device__ __forceinline__ void unpack2(unsigned long long v, float& lo, float& hi) {
    asm("mov.b64 {%0, %1}, %2;" : "=f"(lo), "=f"(hi) : "l"(v));
}
__device__ __forceinline__ unsigned long long ffma2(
    unsigned long long a, unsigned long long b, unsigned long long c) {
    unsigned long long d;
    asm("fma.rn.f32x2 %0, %1, %2, %3;" : "=l"(d) : "l"(a), "l"(b), "l"(c));
    return d;
}

// ====== GEMM (3-way merged): C[z][m,n] = bias[z][n] + sum_k A[m,k]*W[n,k] ======
// Single ascending-k FMA chain per element — bitwise-exact vs reference. DO NOT reorder.
// Double-buffered smem, early global prefetch, ONE __syncthreads per stage.
__global__ __launch_bounds__(256) void gemm3_kernel(
    const float* __restrict__ A,
    const float* __restrict__ W0, const float* __restrict__ W1, const float* __restrict__ W2,
    const float* __restrict__ b0, const float* __restrict__ b1, const float* __restrict__ b2,
    float* __restrict__ C0, float* __restrict__ C1, float* __restrict__ C2,
    int K, int Nn)
{
    const float* W    = (blockIdx.z == 0) ? W0 : (blockIdx.z == 1) ? W1 : W2;
    const float* bias = (blockIdx.z == 0) ? b0 : (blockIdx.z == 1) ? b1 : b2;
    float*       C    = (blockIdx.z == 0) ? C0 : (blockIdx.z == 1) ? C1 : C2;

    __shared__ float As[2][8][128];
    __shared__ float Bs[2][8][128];
    const int tid  = threadIdx.x;
    const int tx   = tid & 15;
    const int ty   = tid >> 4;
    const int m0   = blockIdx.y * 128;
    const int n0   = blockIdx.x * 128;
    const int arow = tid >> 1;
    const int ak   = (tid & 1) * 4;

    const float* Aptr = A + (size_t)(m0 + arow) * K + ak;
    const float* Wptr = W + (size_t)(n0 + arow) * K + ak;

    unsigned long long acc2[8][4];
#pragma unroll
    for (int i = 0; i < 8; i++)
#pragma unroll
        for (int j = 0; j < 4; j++) acc2[i][j] = 0ULL;

    float4 av = *(const float4*)(Aptr);
    float4 wv = *(const float4*)(Wptr);
    As[0][ak + 0][arow] = av.x; As[0][ak + 1][arow] = av.y;
    As[0][ak + 2][arow] = av.z; As[0][ak + 3][arow] = av.w;
    Bs[0][ak + 0][arow] = wv.x; Bs[0][ak + 1][arow] = wv.y;
    Bs[0][ak + 2][arow] = wv.z; Bs[0][ak + 3][arow] = wv.w;
    __syncthreads();

    int buf = 0;
    for (int k0 = 0; k0 < K; k0 += 8) {
        const bool more = (k0 + 8 < K);
        if (more) {                       // issue next-stage loads EARLY
            av = *(const float4*)(Aptr + k0 + 8);
            wv = *(const float4*)(Wptr + k0 + 8);
        }
#pragma unroll
        for (int kk = 0; kk < 8; kk++) {          // ascending k
            float a[8];
            *(float4*)&a[0] = *(const float4*)&As[buf][kk][ty * 8 + 0];
            *(float4*)&a[4] = *(const float4*)&As[buf][kk][ty * 8 + 4];
            const ulonglong2 b01 = *(const ulonglong2*)&Bs[buf][kk][tx * 8 + 0];
            const ulonglong2 b23 = *(const ulonglong2*)&Bs[buf][kk][tx * 8 + 4];
            unsigned long long b2[4];
            b2[0] = b01.x; b2[1] = b01.y; b2[2] = b23.x; b2[3] = b23.y;
#pragma unroll
            for (int i = 0; i < 8; i++) {
                const unsigned long long a2 = pack2(a[i], a[i]);
#pragma unroll
                for (int j = 0; j < 4; j++)
                    acc2[i][j] = ffma2(a2, b2[j], acc2[i][j]);
            }
        }
        if (more) {
            const int nb = buf ^ 1;
            As[nb][ak + 0][arow] = av.x; As[nb][ak + 1][arow] = av.y;
            As[nb][ak + 2][arow] = av.z; As[nb][ak + 3][arow] = av.w;
            Bs[nb][ak + 0][arow] = wv.x; Bs[nb][ak + 1][arow] = wv.y;
            Bs[nb][ak + 2][arow] = wv.z; Bs[nb][ak + 3][arow] = wv.w;
            __syncthreads();
            buf = nb;
        }
    }

#pragma unroll
    for (int i = 0; i < 8; i++) {
        float* cp = C + (size_t)(m0 + ty * 8 + i) * Nn + n0 + tx * 8;
#pragma unroll
        for (int j = 0; j < 4; j++) {
            float c0, c1;
            unpack2(acc2[i][j], c0, c1);
            cp[2 * j + 0] = __fadd_rn(c0, bias[n0 + tx * 8 + 2 * j + 0]);
            cp[2 * j + 1] = __fadd_rn(c1, bias[n0 + tx * 8 + 2 * j + 1]);
        }
    }
}

// ===== LayerNorm + LIF (3-way merged), XLA:CPU NEON-VF8 reduce — order bitwise-fixed =====
// gamma/beta via __ldg (L1-resident) instead of 48 registers -> higher occupancy.
__global__ __launch_bounds__(256) void ln3_kernel(
    const float* __restrict__ H0, const float* __restrict__ H1, const float* __restrict__ H2,
    float* __restrict__ S0, float* __restrict__ S1, float* __restrict__ S2,
    const float* __restrict__ g0_, const float* __restrict__ g1_, const float* __restrict__ g2_,
    const float* __restrict__ e0_, const float* __restrict__ e1_, const float* __restrict__ e2_,
    unsigned long long* __restrict__ M0, unsigned long long* __restrict__ M1,
    unsigned long long* __restrict__ M2, float thr)
{
    const float* Hin = (blockIdx.y == 0) ? H0 : (blockIdx.y == 1) ? H1 : H2;
    float*      Sout = (blockIdx.y == 0) ? S0 : (blockIdx.y == 1) ? S1 : S2;
    const float* gam = (blockIdx.y == 0) ? g0_ : (blockIdx.y == 1) ? g1_ : g2_;
    const float* bet = (blockIdx.y == 0) ? e0_ : (blockIdx.y == 1) ? e1_ : e2_;
    unsigned long long* Mout = (blockIdx.y == 0) ? M0 : (blockIdx.y == 1) ? M1 : M2;

    __shared__ float xs[8][768];
    const int w   = threadIdx.x >> 5;
    const int j   = threadIdx.x & 31;
    const int row0 = blockIdx.x * 8 + w;
    const int b   = row0 / L_;
    const int l   = row0 % L_;

    float v[24];
#pragma unroll
    for (int k = 0; k < 24; k++) v[k] = 0.0f;

    for (int t = 0; t < T_; t++) {
        const size_t row = (size_t)(b * T_ + t) * L_ + l;
        const size_t off = row * D_;
#pragma unroll
        for (int k = 0; k < 24; k++)
            xs[w][j + 32 * k] = Hin[off + j + 32 * k];
        __syncwarp();

        // ---- mean: 8-lane stride-8 serial partials (EXACT order) ----
        float p = 0.0f;
        if (j < 8) {
#pragma unroll 8
            for (int i = 0; i < 96; i++)
                p = __fadd_rn(p, xs[w][8 * i + j]);
        }
        p = __fadd_rn(p, __shfl_xor_sync(0xffffffffu, p, 4));
        p = __fadd_rn(p, __shfl_xor_sync(0xffffffffu, p, 1));
        p = __fadd_rn(p, __shfl_xor_sync(0xffffffffu, p, 2));
        const float sum = __shfl_sync(0xffffffffu, p, 0);
        const float m = __fdiv_rn(sum, 768.0f);

        // ---- variance (EXACT order) ----
        float q = 0.0f;
        if (j < 8) {
#pragma unroll 8
            for (int i = 0; i < 96; i++) {
                const float d = __fsub_rn(xs[w][8 * i + j], m);
                q = __fadd_rn(q, __fmul_rn(d, d));
            }
        }
        q = __fadd_rn(q, __shfl_xor_sync(0xffffffffu, q, 4));
        q = __fadd_rn(q, __shfl_xor_sync(0xffffffffu, q, 1));
        q = __fadd_rn(q, __shfl_xor_sync(0xffffffffu, q, 2));
        const float sum2 = __shfl_sync(0xffffffffu, q, 0);
        const float var = __fdiv_rn(sum2, 768.0f);
        const float rs  = __fsqrt_rn(__fadd_rn(var, 1e-5f));

        // ---- normalize + LIF (EXACT op sequence; *0.5f == /2 bitwise) ----
        unsigned btmp = 0u;
#pragma unroll
        for (int k = 0; k < 24; k++) {
            const float x = xs[w][j + 32 * k];
            const float gk  = __ldg(&gam[j + 32 * k]);
            const float bek = __ldg(&bet[j + 32 * k]);
            const float d = __fsub_rn(x, m);
            const float h = __fadd_rn(__fmul_rn(__fdiv_rn(d, rs), gk), bek);
            v[k] = __fadd_rn(v[k], __fmul_rn(__fsub_rn(h, v[k]), 0.5f));
            const bool f = (__fsub_rn(v[k], thr) >= 0.0f);
            if (Sout) Sout[off + j + 32 * k] = f ? 1.0f : 0.0f;
            v[k] = f ? 0.0f : v[k];
            if (Mout) {
                const unsigned bal = __ballot_sync(0xffffffffu, f);
                if ((k & 1) == 0) btmp = bal;
                else if (j == (k >> 1))
                    Mout[row * H_ + (k >> 1)] =
                        (unsigned long long)btmp | ((unsigned long long)bal << 32);
            }
        }
        __syncwarp();
    }
}

// ===== attention: QK via mask popcount, AV via dp4a; V expanded from masks =====
// All values exact integers — bit-equivalent to the float formulation.
__global__ __launch_bounds__(256) void attn_kernel(
    const unsigned long long* __restrict__ Mq, const unsigned long long* __restrict__ Mk,
    const unsigned long long* __restrict__ Mv, float* __restrict__ O)
{
    __shared__ unsigned long long Km[64];
    __shared__ unsigned long long Vm[64];
    __shared__ __align__(16) unsigned Vs8[64][16];   // [d][mg]: 4 int8 m's per word
    const int h = blockIdx.x;
    const int t = blockIdx.y;
    const int b = blockIdx.z;
    const size_t rowbase = (size_t)(b * T_ + t) * L_;
    const int col = h * DH_;
    const int l = threadIdx.x;

    const unsigned long long qmask = Mq[(rowbase + l) * H_ + h];

    int o32[64];
#pragma unroll
    for (int d = 0; d < 64; d++) o32[d] = 0;

    for (int m0 = 0; m0 < L_; m0 += 64) {
        __syncthreads();                  // protect Km/Vm/Vs8 from prior consumers
        if (threadIdx.x < 64)
            Km[threadIdx.x] = Mk[(rowbase + m0 + threadIdx.x) * H_ + h];
        else if (threadIdx.x < 128)
            Vm[threadIdx.x - 64] = Mv[(rowbase + m0 + threadIdx.x - 64) * H_ + h];
        __syncthreads();
        // expand V masks to int8 d-major: Vs8[d][mg] = bytes of m = 4mg..4mg+3
        for (int wv = threadIdx.x; wv < 1024; wv += 256) {
            const int d  = wv >> 4;
            const int mg = wv & 15;
            const unsigned b0 = (unsigned)(Vm[4 * mg + 0] >> d) & 1u;
            const unsigned b1 = (unsigned)(Vm[4 * mg + 1] >> d) & 1u;
            const unsigned b2 = (unsigned)(Vm[4 * mg + 2] >> d) & 1u;
            const unsigned b3 = (unsigned)(Vm[4 * mg + 3] >> d) & 1u;
            Vs8[d][mg] = b0 | (b1 << 8) | (b2 << 16) | (b3 << 24);
        }
        __syncthreads();

#pragma unroll 1
        for (int mq = 0; mq < 4; mq++) {     // 16 m's per mq
            unsigned a4[4];
#pragma unroll
            for (int r = 0; r < 4; r++) {
                const int mg = mq * 4 + r;
                const int a0 = __popcll(qmask & Km[4 * mg + 0]);
                const int a1 = __popcll(qmask & Km[4 * mg + 1]);
                const int a2 = __popcll(qmask & Km[4 * mg + 2]);
                const int a3 = __popcll(qmask & Km[4 * mg + 3]);
                a4[r] = (unsigned)a0 | ((unsigned)a1 << 8) |
                        ((unsigned)a2 << 16) | ((unsigned)a3 << 24);
            }
#pragma unroll
            for (int d = 0; d < 64; d++) {
                const uint4 vv = *(const uint4*)&Vs8[d][mq * 4];
                int acc = o32[d];
                acc = __dp4a((int)a4[0], (int)vv.x, acc);
                acc = __dp4a((int)a4[1], (int)vv.y, acc);
                acc = __dp4a((int)a4[2], (int)vv.z, acc);
                acc = __dp4a((int)a4[3], (int)vv.w, acc);
                o32[d] = acc;
            }
        }
    }

    float* op = O + (rowbase + l) * D_ + col;
#pragma unroll
    for (int d = 0; d < 64; d += 4) {
        float4 v4;
        v4.x = __fmul_rn((float)o32[d + 0], 0.25f);   // exact
        v4.y = __fmul_rn((float)o32[d + 1], 0.25f);
        v4.z = __fmul_rn((float)o32[d + 2], 0.25f);
        v4.w = __fmul_rn((float)o32[d + 3], 0.25f);
        *(float4*)(op + d) = v4;
    }
}

// ========== LIF over T on O (thr = 0.5, exact dyadic), in place, float4 ==========
__global__ __launch_bounds__(256) void lif2_kernel(float4* __restrict__ IO)
{
    const int nq = (L_ * D_) / 4;
    const int idx = blockIdx.x * 256 + threadIdx.x;   // over B*L*D/4
    const int b = idx / nq;
    const int r = idx % nq;
    float4 v = make_float4(0.f, 0.f, 0.f, 0.f);
#pragma unroll
    for (int t = 0; t < T_; t++) {
        const size_t off = ((size_t)(b * T_ + t)) * (size_t)nq + r;
        float4 x = IO[off];
        v.x = __fadd_rn(v.x, __fmul_rn(__fsub_rn(x.x, v.x), 0.5f));
        v.y = __fadd_rn(v.y, __fmul_rn(__fsub_rn(x.y, v.y), 0.5f));
        v.z = __fadd_rn(v.z, __fmul_rn(__fsub_rn(x.z, v.z), 0.5f));
        v.w = __fadd_rn(v.w, __fmul_rn(__fsub_rn(x.w, v.w), 0.5f));
        const bool f0 = (v.x >= 0.5f), f1 = (v.y >= 0.5f);
        const bool f2 = (v.z >= 0.5f), f3 = (v.w >= 0.5f);
        IO[off] = make_float4(f0 ? 1.f : 0.f, f1 ? 1.f : 0.f,
                              f2 ? 1.f : 0.f, f3 ? 1.f : 0.f);
        v.x = f0 ? 0.f : v.x;
        v.y = f1 ? 0.f : v.y;
        v.z = f2 ? 0.f : v.z;
        v.w = f3 ? 0.f : v.w;
    }
}

// ================= launch =================
extern "C" void kernel_launch(void* const* d_in, const int* in_sizes, int n_in,
                              void* d_out, int out_size)
{
    (void)in_sizes; (void)n_in; (void)out_size;
    const float* x   = (const float*)d_in[0];
    const float* qw  = (const float*)d_in[1];
    const float* qb  = (const float*)d_in[2];
    const float* qg  = (const float*)d_in[3];
    const float* qbe = (const float*)d_in[4];
    const float* kw  = (const float*)d_in[5];
    const float* kb  = (const float*)d_in[6];
    const float* kg  = (const float*)d_in[7];
    const float* kbe = (const float*)d_in[8];
    const float* vw  = (const float*)d_in[9];
    const float* vb  = (const float*)d_in[10];
    const float* vg  = (const float*)d_in[11];
    const float* vbe = (const float*)d_in[12];
    const float* lw  = (const float*)d_in[13];
    const float* lb  = (const float*)d_in[14];
    const float* lg  = (const float*)d_in[15];
    const float* lbe = (const float*)d_in[16];

    float *Hq, *Hk, *Hv, *O, *Y;
    unsigned long long *Mq, *Mk, *Mv;
    cudaGetSymbolAddress((void**)&Hq, g_Hq);
    cudaGetSymbolAddress((void**)&Hk, g_Hk);
    cudaGetSymbolAddress((void**)&Hv, g_Hv);
    cudaGetSymbolAddress((void**)&O,  g_O);
    cudaGetSymbolAddress((void**)&Y,  g_Y);
    cudaGetSymbolAddress((void**)&Mq, g_Mq);
    cudaGetSymbolAddress((void**)&Mk, g_Mk);
    cudaGetSymbolAddress((void**)&Mv, g_Mv);

    // Q/K/V projections in ONE launch
    gemm3_kernel<<<dim3(D_ / 128, N_ / 128, 3), 256>>>(
        x, qw, kw, vw, qb, kb, vb, Hq, Hk, Hv, D_, D_);

    // 3 LNs in ONE launch: all emit masks only (no float spike stores)
    ln3_kernel<<<dim3((B_ * L_) / 8, 3), 256>>>(
        Hq, Hk, Hv,
        nullptr, nullptr, nullptr,
        qg, kg, vg, qbe, kbe, vbe,
        Mq, Mk, Mv, 1.0f);

    // attention per (h,t,b) — mask QK + mask-expanded dp4a AV (exact integers)
    attn_kernel<<<dim3(H_, T_, B_), 256>>>(Mq, Mk, Mv, O);

    // LIF (thr=0.5) over T, exact dyadic, in place -> binary
    lif2_kernel<<<(B_ * L_ * D_) / 1024, 256>>>((float4*)O);

    // final linear on binary spikes
    gemm3_kernel<<<dim3(D_ / 128, N_ / 128, 1), 256>>>(
        O, lw, lw, lw, lb, lb, lb, Y, Y, Y, D_, D_);

    // final LN + LIF (thr=1) -> output [B,T,L,D]; float output, no masks
    ln3_kernel<<<dim3((B_ * L_) / 8, 1), 256>>>(
        Y, Y, Y,
        (float*)d_out, (float*)d_out, (float*)d_out,
        lg, lg, lg, lbe, lbe, lbe,
        nullptr, nullptr, nullptr, 1.0f);
}